// round 8
// baseline (speedup 1.0000x reference)
#include <cuda_runtime.h>
#include <stdint.h>
#include <math.h>

#define NPV   32768          // nodes in perturbed graph
#define NNV   128            // nodes in non-perturbed graph
#define EPV   524288         // edges p
#define ENV   2048           // edges np
#define CH    128            // channels
#define WALKN 7
#define BATN  256
#define TOTP  (EPV + NPV)    // CSR entries p (edges + self loops)
#define TOTN  (ENV + NNV)
#define CC    (CH * CH)

// ---------------- device scratch (static, no allocation) ----------------
// All state consumed-and-restored each run: zero at load, every kernel that
// reads a "must be zero at start" buffer re-zeroes it after the read, so
// every replay starts from the identical state.
static __device__ int   g_deg_p[NPV];
static __device__ int   g_deg_n[NNV];
static __device__ float g_dinv_p[NPV];
static __device__ float g_dinv_n[NNV];
static __device__ int   g_rs_p[NPV + 1];
static __device__ int   g_rs_n[NNV + 1];
static __device__ int   g_cur_p[NPV];
static __device__ int   g_cur_n[NNV];
static __device__ int   g_bsum[32];
static __device__ int2  g_colw_p[TOTP];          // {src, float_bits(norm)}
static __device__ int2  g_colw_n[TOTN];
static __device__ float g_g[2][NPV * CH];        // ping-pong g = A^t x_p
static __device__ float g_gn[2][NNV * CH];
static __device__ float g_c[2][NPV];             // ping-pong c = A^t 1
static __device__ float g_cn[2][NNV];
static __device__ float g_PT[(WALKN + 1) * CC];  // (W^t)^T
static __device__ float g_Bv[(WALKN + 1) * CH];  // b^T W^t
static __device__ float g_ptr[WALKN * BATN];     // block traces of g_t W^t
static __device__ float g_ntr[WALKN];
static __device__ float g_q [WALKN * BATN];      // q'_a = <c_a block, B_a>
static __device__ float g_qn[WALKN];
static __device__ int   g_not64_p;
static __device__ int   g_not64_n;
static __device__ int   g_bnz;                   // any(b != 0)?

__device__ __forceinline__ int eget(const void* p, int is64, int i) {
    return is64 ? (int)((const long long*)p)[i] : ((const int*)p)[i];
}

// ---------------- dtype detection only (int64 vs int32 edges) ----------------
// First 2*E 32-bit words exist in BOTH layouts. If layout is int64, odd words
// are high halves of values < 32768 -> all zero. EPV, ENV multiples of 256.
__global__ void k_prep(const void* __restrict__ eip, const void* __restrict__ ein) {
    int i = blockIdx.x * blockDim.x + threadIdx.x;
    bool nz;
    int which;
    if (i < EPV) { nz = ((const int*)eip)[2 * i + 1] != 0; which = 1; }
    else         { nz = ((const int*)ein)[2 * (i - EPV) + 1] != 0; which = 2; }
    unsigned m = __ballot_sync(0xffffffffu, nz);
    if (m && (threadIdx.x & 31) == 0)
        atomicOr(which == 1 ? &g_not64_p : &g_not64_n, 1);
}

// ---------------- degree count at dst ----------------
__global__ void k_deg(const void* __restrict__ eip, const void* __restrict__ ein) {
    int i = blockIdx.x * blockDim.x + threadIdx.x;
    if (i < EPV) {
        int d = eget(eip, !g_not64_p, EPV + i);
        atomicAdd(&g_deg_p[d], 1);
    } else {
        int j = i - EPV;
        int d = eget(ein, !g_not64_n, ENV + j);
        atomicAdd(&g_deg_n[d], 1);
    }
}

// ---------------- scan pass 1: per-window local scan (+ full np scan) -------
// Blocks 0..31: p-graph 1024-wide windows. Block 32: entire np graph.
// g_deg is zeroed right after the read (restores load-time state).
__global__ void k_scan1() {
    __shared__ int ws[32];
    int t = threadIdx.x, lane = t & 31, w = t >> 5;
    if (blockIdx.x < 32) {
        int i = blockIdx.x * 1024 + t;
        int L = g_deg_p[i] + 1;                // + self loop
        g_deg_p[i] = 0;
        g_dinv_p[i] = rsqrtf((float)L);
        int s = L;
        for (int o = 1; o < 32; o <<= 1) {
            int u = __shfl_up_sync(0xffffffffu, s, o);
            if (lane >= o) s += u;
        }
        if (lane == 31) ws[w] = s;
        __syncthreads();
        if (w == 0) {
            int v = ws[lane], ss = v;
            for (int o = 1; o < 32; o <<= 1) {
                int u = __shfl_up_sync(0xffffffffu, ss, o);
                if (lane >= o) ss += u;
            }
            ws[lane] = ss - v;                 // exclusive warp offsets
        }
        __syncthreads();
        int ex = s - L + ws[w];
        g_rs_p[i] = ex;                        // window-local exclusive
        if (t == 1023) g_bsum[blockIdx.x] = ex + L;
    } else {
        int valid = t < NNV;
        int L = 1;
        if (valid) {
            L = g_deg_n[t] + 1;
            g_deg_n[t] = 0;
            g_dinv_n[t] = rsqrtf((float)L);
        }
        int s = L;
        for (int o = 1; o < 32; o <<= 1) {
            int u = __shfl_up_sync(0xffffffffu, s, o);
            if (lane >= o) s += u;
        }
        if (lane == 31 && w < 4) ws[w] = s;
        __syncthreads();
        if (valid) {
            int off = 0;
            for (int k = 0; k < 4; k++) off += (k < w) ? ws[k] : 0;
            int ex = s - L + off;
            g_rs_n[t] = ex;
            g_cur_n[t] = ex;
        }
        if (t == 0) g_rs_n[NNV] = TOTN;
    }
}

// ---------------- scan pass 2: add window offsets (computed locally) --------
__global__ void k_scan3() {                    // grid 128, block 256
    __shared__ int soff;
    int t = threadIdx.x;
    if (t < 32) {
        int v = g_bsum[t], s = v;
        for (int o = 1; o < 32; o <<= 1) {
            int u = __shfl_up_sync(0xffffffffu, s, o);
            if (t >= o) s += u;
        }
        if (t == (int)(blockIdx.x >> 2)) soff = s - v;  // exclusive offset of my window
    }
    __syncthreads();
    int i = blockIdx.x * 256 + t;
    int v = g_rs_p[i] + soff;
    g_rs_p[i] = v;
    g_cur_p[i] = v;
    if (i == 0) g_rs_p[NPV] = TOTP;
}

// ---------------- CSR fill (edges + self loops, with norms) ----------------
__global__ void k_fill(const void* __restrict__ eip, const void* __restrict__ ein) {
    int i = blockIdx.x * blockDim.x + threadIdx.x;
    if (i < EPV) {
        int is64 = !g_not64_p;
        int s = eget(eip, is64, i);
        int d = eget(eip, is64, EPV + i);
        float w = g_dinv_p[s] * g_dinv_p[d];
        int pos = atomicAdd(&g_cur_p[d], 1);
        g_colw_p[pos] = make_int2(s, __float_as_int(w));
    } else if (i < EPV + NPV) {
        int n = i - EPV;
        float di = g_dinv_p[n];
        int pos = atomicAdd(&g_cur_p[n], 1);
        g_colw_p[pos] = make_int2(n, __float_as_int(di * di));
    } else if (i < EPV + NPV + ENV) {
        int j = i - EPV - NPV;
        int is64 = !g_not64_n;
        int s = eget(ein, is64, j);
        int d = eget(ein, is64, ENV + j);
        float w = g_dinv_n[s] * g_dinv_n[d];
        int pos = atomicAdd(&g_cur_n[d], 1);
        g_colw_n[pos] = make_int2(s, __float_as_int(w));
    } else if (i < EPV + NPV + ENV + NNV) {
        int n = i - EPV - NPV - ENV;
        float di = g_dinv_n[n];
        int pos = atomicAdd(&g_cur_n[n], 1);
        g_colw_n[pos] = make_int2(n, __float_as_int(di * di));
    }
}

// ---------------- all W powers in ONE kernel + c-vector init ---------------
// P_t[r,:] = P_{t-1}[r,:] @ W is independent per row r. Block r keeps its row
// in SMEM and iterates all WALKN powers; W is L1-resident after first sweep.
// Block CH handles the bias row b^T W^t and publishes the b!=0 flag.
// Also grid-strides the g_c/g_cn = 1 init (needed before the first agg).
__global__ void k_wpow_all(const float* __restrict__ W, const float* __restrict__ bg) {
    __shared__ float prev[CH];
    int c = threadIdx.x;
    int r = blockIdx.x;
    int idx = r * CH + c;                      // 0 .. 129*128-1
    for (int i = idx; i < NPV; i += (CH + 1) * CH) g_c[0][i] = 1.0f;
    if (idx < NNV) g_cn[0][idx] = 1.0f;

    prev[c] = (r < CH) ? ((c == r) ? 1.0f : 0.0f) : bg[c];
    if (r == CH) {
        int nz = __syncthreads_or(prev[c] != 0.0f);
        if (c == 0) g_bnz = nz;
    }
    __syncthreads();
    for (int t = 1; t <= WALKN; t++) {
        float acc = 0.0f;
#pragma unroll 16
        for (int m = 0; m < CH; m++) acc = fmaf(prev[m], W[m * CH + c], acc);
        __syncthreads();
        prev[c] = acc;
        if (r < CH) g_PT[t * CC + c * CH + r] = acc;   // transposed for fused trace
        else        g_Bv[t * CH + c] = acc;
        __syncthreads();
    }
}

// ---------------- main per-step kernel: g <- A g, (c <- A c), fused traces --
__global__ void __launch_bounds__(256) k_agg(const float* __restrict__ xp,
                                             const float* __restrict__ xnp,
                                             int a, int last) {
    int gw   = blockIdx.x * 8 + (threadIdx.x >> 5);   // warp per dst row
    int lane = threadIdx.x & 31;
    int pa = (a - 1) & 1, ca = a & 1;
    int cpath = g_bnz && !last;                       // b==0 fast path (uniform)

    if (gw < NPV) {
        const float4* g4  = (const float4*)((a == 1) ? xp : g_g[pa]);
        const float*  cin = g_c[pa];
        int s0 = g_rs_p[gw], s1 = g_rs_p[gw + 1];
        float ax = 0.f, ay = 0.f, az = 0.f, aw = 0.f, cacc = 0.f;
        int e = s0;
        for (; e + 2 <= s1; e += 2) {                 // 2-deep pipeline (MLP)
            int2 cw0 = g_colw_p[e];
            int2 cw1 = g_colw_p[e + 1];
            float4 v0 = g4[cw0.x * 32 + lane];
            float4 v1 = g4[cw1.x * 32 + lane];
            float w0 = __int_as_float(cw0.y), w1 = __int_as_float(cw1.y);
            ax = fmaf(w0, v0.x, ax); ay = fmaf(w0, v0.y, ay);
            az = fmaf(w0, v0.z, az); aw = fmaf(w0, v0.w, aw);
            ax = fmaf(w1, v1.x, ax); ay = fmaf(w1, v1.y, ay);
            az = fmaf(w1, v1.z, az); aw = fmaf(w1, v1.w, aw);
            if (cpath && lane == 0) cacc += w0 * cin[cw0.x] + w1 * cin[cw1.x];
        }
        if (e < s1) {
            int2 cw0 = g_colw_p[e];
            float4 v0 = g4[cw0.x * 32 + lane];
            float w0 = __int_as_float(cw0.y);
            ax = fmaf(w0, v0.x, ax); ay = fmaf(w0, v0.y, ay);
            az = fmaf(w0, v0.z, az); aw = fmaf(w0, v0.w, aw);
            if (cpath && lane == 0) cacc += w0 * cin[cw0.x];
        }
        if (!last)   // g_WALKN never consumed downstream
            ((float4*)g_g[ca])[gw * 32 + lane] = make_float4(ax, ay, az, aw);

        // fused block trace: row r=gw contributes  g[r,:] . W^a[:, r&127]
        int k = gw & 127, bb = gw >> 7;
        float4 wt = ((const float4*)(g_PT + a * CC + k * CH))[lane];
        float part = ax * wt.x + ay * wt.y + az * wt.z + aw * wt.w;
        part += __shfl_xor_sync(0xffffffffu, part, 16);
        part += __shfl_xor_sync(0xffffffffu, part, 8);
        part += __shfl_xor_sync(0xffffffffu, part, 4);
        part += __shfl_xor_sync(0xffffffffu, part, 2);
        part += __shfl_xor_sync(0xffffffffu, part, 1);
        if (lane == 0) {
            atomicAdd(&g_ptr[(a - 1) * BATN + bb], part);
            if (cpath) {
                g_c[ca][gw] = cacc;
                atomicAdd(&g_q[(a - 1) * BATN + bb], cacc * g_Bv[a * CH + k]);
            }
        }
    } else {
        int w2 = gw - NPV;                            // np graph, 128 dst rows
        const float4* g4  = (const float4*)((a == 1) ? xnp : g_gn[pa]);
        const float*  cin = g_cn[pa];
        int s0 = g_rs_n[w2], s1 = g_rs_n[w2 + 1];
        float ax = 0.f, ay = 0.f, az = 0.f, aw = 0.f, cacc = 0.f;
        for (int e = s0; e < s1; e++) {
            int2 cw0 = g_colw_n[e];
            float4 v0 = g4[cw0.x * 32 + lane];
            float w0 = __int_as_float(cw0.y);
            ax = fmaf(w0, v0.x, ax); ay = fmaf(w0, v0.y, ay);
            az = fmaf(w0, v0.z, az); aw = fmaf(w0, v0.w, aw);
            if (cpath && lane == 0) cacc += w0 * cin[cw0.x];
        }
        if (!last)
            ((float4*)g_gn[ca])[w2 * 32 + lane] = make_float4(ax, ay, az, aw);
        float4 wt = ((const float4*)(g_PT + a * CC + w2 * CH))[lane];
        float part = ax * wt.x + ay * wt.y + az * wt.z + aw * wt.w;
        part += __shfl_xor_sync(0xffffffffu, part, 16);
        part += __shfl_xor_sync(0xffffffffu, part, 8);
        part += __shfl_xor_sync(0xffffffffu, part, 4);
        part += __shfl_xor_sync(0xffffffffu, part, 2);
        part += __shfl_xor_sync(0xffffffffu, part, 1);
        if (lane == 0) {
            atomicAdd(&g_ntr[a - 1], part);
            if (cpath) {
                g_cn[ca][w2] = cacc;
                atomicAdd(&g_qn[a - 1], cacc * g_Bv[a * CH + w2]);
            }
        }
    }
}

// ---------------- epilogue: bias corr, standardize, MLP, sigmoid, reset ----
__device__ __forceinline__ float blk_sum(float v, float* sm) {
    int t = threadIdx.x, lane = t & 31, w = t >> 5;
    v += __shfl_xor_sync(0xffffffffu, v, 16);
    v += __shfl_xor_sync(0xffffffffu, v, 8);
    v += __shfl_xor_sync(0xffffffffu, v, 4);
    v += __shfl_xor_sync(0xffffffffu, v, 2);
    v += __shfl_xor_sync(0xffffffffu, v, 1);
    if (lane == 0) sm[w] = v;
    __syncthreads();
    if (w == 0) {
        float r = (lane < 8) ? sm[lane] : 0.0f;
        r += __shfl_xor_sync(0xffffffffu, r, 4);
        r += __shfl_xor_sync(0xffffffffu, r, 2);
        r += __shfl_xor_sync(0xffffffffu, r, 1);
        if (lane == 0) sm[8] = r;
    }
    __syncthreads();
    float out = sm[8];
    __syncthreads();
    return out;
}

__global__ void k_epi(const float* __restrict__ y,  const float* __restrict__ bg,
                      const float* __restrict__ W1, const float* __restrict__ b1,
                      const float* __restrict__ W2, const float* __restrict__ b2,
                      float* __restrict__ out) {
    __shared__ float sm[9];
    int b = threadIdx.x;
    float sumb = 0.f;
    for (int k = 0; k < CH; k++) sumb += bg[k];
    float ysc = (y[b] - 0.5f) * 2.0f;

    float v[WALKN];
    float cp = 0.f, cn = 0.f;
    for (int s = 0; s < WALKN; s++) {
        float qp = (s == 0) ? sumb : g_q[(s - 1) * BATN + b];
        float qn = (s == 0) ? sumb : g_qn[s - 1];
        cp += qp; cn += qn;
        float pv = g_ptr[s * BATN + b] + cp;
        float nv = g_ntr[s] + cn;
        v[s] = (pv - nv) * ysc;
    }
    for (int s = 0; s < WALKN; s++) {
        float mu = blk_sum(v[s], sm) * (1.0f / BATN);
        float d = v[s] - mu;
        float var = blk_sum(d * d, sm) * (1.0f / (BATN - 1));
        v[s] = d * rsqrtf(var) ;
        // match sqrt-divide semantics exactly:
        v[s] = d / sqrtf(var);
    }
    float o2 = b2[0];
    for (int j = 0; j < 15; j++) {
        float h = b1[j];
        for (int s = 0; s < WALKN; s++) h = fmaf(v[s], W1[s * 15 + j], h);
        h = fmaxf(h, 0.0f);
        o2 = fmaf(h, W2[j], o2);
    }
    out[b] = 1.0f / (1.0f + expf(-o2));

    // restore load-time state for the next identical replay
    __syncthreads();
    for (int s = 0; s < WALKN; s++) { g_ptr[s * BATN + b] = 0.0f; g_q[s * BATN + b] = 0.0f; }
    if (b < WALKN) { g_ntr[b] = 0.0f; g_qn[b] = 0.0f; }
    if (b == 0)    { g_not64_p = 0; g_not64_n = 0; }
}

// ---------------- launch ----------------
extern "C" void kernel_launch(void* const* d_in, const int* in_sizes, int n_in,
                              void* d_out, int out_size) {
    const float* x_p  = (const float*)d_in[0];
    const float* x_np = (const float*)d_in[1];
    const float* y    = (const float*)d_in[2];
    const void*  eip  = d_in[3];
    const void*  ein  = d_in[4];
    const float* W    = (const float*)d_in[5];
    const float* bg   = (const float*)d_in[6];
    const float* W1   = (const float*)d_in[7];
    const float* b1   = (const float*)d_in[8];
    const float* W2   = (const float*)d_in[9];
    const float* b2   = (const float*)d_in[10];
    float* out = (float*)d_out;

    k_prep<<<(EPV + ENV) / 256, 256>>>(eip, ein);
    k_deg<<<(EPV + ENV) / 256, 256>>>(eip, ein);
    k_scan1<<<33, 1024>>>();
    k_scan3<<<NPV / 256, 256>>>();
    k_wpow_all<<<CH + 1, CH>>>(W, bg);
    k_fill<<<(EPV + NPV + ENV + NNV + 255) / 256, 256>>>(eip, ein);
    for (int a = 1; a <= WALKN; a++)
        k_agg<<<(NPV + NNV) / 8, 256>>>(x_p, x_np, a, a == WALKN);
    k_epi<<<1, BATN>>>(y, bg, W1, b1, W2, b2, out);
    (void)in_sizes; (void)n_in; (void)out_size;
}